// round 4
// baseline (speedup 1.0000x reference)
#include <cuda_runtime.h>
#include <cuda_bf16.h>

// SpanGenerator: out = concat_{L=1..8} [ sliding sums of length L starting at
// token index 1 ] over input [B=8, S=512, D=768] fp32.
// span(L, i) = sum_{k=1+i}^{L+i} x[b, k, :],  valid for 0 <= i <= S-1-L.
// Output row offset for span-length L: OFF[L-1] = sum_{l<L} (S - l).

#define BB 8
#define SS 512
#define DD 768
#define D4 (DD / 4)      // 192 float4 lanes
#define NROWS 4060       // sum_{L=1..8} (512 - L)
#define ICHUNK 8

__global__ __launch_bounds__(D4, 8)
void span_kernel(const float4* __restrict__ in, float4* __restrict__ out) {
    const int d  = threadIdx.x;            // 0..191 (float4 index in D)
    const int b  = blockIdx.y;             // batch
    const int i0 = blockIdx.x * ICHUNK;    // start span-index for this chunk

    const float4* src = in  + (size_t)b * SS * D4 + d;
    float4*       dstb = out + (size_t)b * NROWS * D4 + d;

    const float4 fzero = make_float4(0.f, 0.f, 0.f, 0.f);

    // Row offsets of each span-length block in the concatenated output.
    const int OFF[8] = {0, 511, 1021, 1530, 2038, 2545, 3051, 3556};

    // Per-L destination pointers for row i0 (advanced by D4 each iteration).
    float4* dstL[8];
#pragma unroll
    for (int L = 0; L < 8; L++) dstL[L] = dstb + (size_t)(OFF[L] + i0) * D4;

    // Sliding window of 8 input rows: w[k] = x[b, 1 + i + k, dquad]
    float4 w[8];
#pragma unroll
    for (int k = 0; k < 7; k++) {
        int s = 1 + i0 + k;
        w[k] = (s < SS) ? src[(size_t)s * D4] : fzero;
    }

    const int iend = min(i0 + ICHUNK, SS - 1);   // i ranges over [0, 510]

    if (i0 + ICHUNK <= SS - 8) {
        // Fast path: every load and all 8 stores are valid for all i in chunk.
#pragma unroll
        for (int t = 0; t < ICHUNK; t++) {
            const int i = i0 + t;
            w[7] = src[(size_t)(i + 8) * D4];

            float4 acc = fzero;
#pragma unroll
            for (int L = 0; L < 8; L++) {
                acc.x += w[L].x;
                acc.y += w[L].y;
                acc.z += w[L].z;
                acc.w += w[L].w;
                dstL[L][0] = acc;
                dstL[L] += D4;
            }
#pragma unroll
            for (int k = 0; k < 7; k++) w[k] = w[k + 1];
        }
    } else {
        // Tail path: guard loads and stores against the sequence end.
        for (int i = i0; i < iend; i++) {
            {
                int s = i + 8;
                w[7] = (s < SS) ? src[(size_t)s * D4] : fzero;
            }
            float4 acc = fzero;
#pragma unroll
            for (int L = 0; L < 8; L++) {
                acc.x += w[L].x;
                acc.y += w[L].y;
                acc.z += w[L].z;
                acc.w += w[L].w;
                if (i + L + 1 < SS) {
                    dstL[L][0] = acc;
                }
                dstL[L] += D4;
            }
#pragma unroll
            for (int k = 0; k < 7; k++) w[k] = w[k + 1];
        }
    }
}

extern "C" void kernel_launch(void* const* d_in, const int* in_sizes, int n_in,
                              void* d_out, int out_size) {
    const float4* in  = (const float4*)d_in[0];   // tensor [8, 512, 768] fp32
    float4*       out = (float4*)d_out;           // [8, 4060, 768] fp32
    (void)in_sizes; (void)n_in; (void)out_size;   // max_span_length fixed at 8

    dim3 grid((SS - 1 + ICHUNK - 1) / ICHUNK, BB);  // (64, 8)
    dim3 block(D4);                                  // 192 threads
    span_kernel<<<grid, block>>>(in, out);
}